// round 8
// baseline (speedup 1.0000x reference)
#include <cuda_runtime.h>
#include <cuda_bf16.h>
#include <cstdint>

#define Nn 4
#define Mm 1024
#define Dd 64
#define Ll 16
#define Bb 4096
#define BL 65536
#define DECAYF 0.999f
#define EPSF 1e-5f
#define COMMITF 0.05f

#define OFF_ZQ   0LL
#define OFF_LOSS 16777216LL
#define OFF_PERP 16777217LL
#define OFF_IDX  16777218LL
#define OFF_EZQ  17039362LL
#define OFF_EMB  33816578LL
#define OFF_CNT  34078722LL
#define OFF_EMW  34082818LL

__device__ float    g_xt[Nn * BL * Dd];
__device__ uint32_t g_xbf[Nn * BL * 32];    // x bf16 pairs, 128B per row
__device__ uint32_t g_ebf[Nn * Mm * 32];    // embedding bf16 pairs, 128B per row
__device__ float    g_xnorm[Nn * BL];
__device__ int      g_idx[Nn * BL];
__device__ float    g_dw[Nn * Mm * Dd];
__device__ int      g_cnt[Nn * Mm];
__device__ float    g_enorm[Nn * Mm];
__device__ int      g_emaxbits[Nn];
__device__ float    g_fcnt[Nn * Mm];
__device__ float    g_losspart[Bb * Nn];

#define SWZ(off) ((off) ^ (((off) >> 3) & 0x70))
#define CP_ASYNC16(dst, src) \
    asm volatile("cp.async.cg.shared.global [%0], [%1], 16;" :: "r"(dst), "l"(src))
#define CP_COMMIT() asm volatile("cp.async.commit_group;" ::: "memory")
#define CP_WAIT(nconst) asm volatile("cp.async.wait_group %0;" :: "n"(nconst) : "memory")
#define LDSM4(r0, r1, r2, r3, addr) \
    asm volatile("ldmatrix.sync.aligned.m8n8.x4.shared.b16 {%0,%1,%2,%3}, [%4];" \
                 : "=r"(r0), "=r"(r1), "=r"(r2), "=r"(r3) : "r"(addr))

__device__ __forceinline__ uint32_t smem_u32(const void* p) {
    uint32_t a;
    asm("{ .reg .u64 t; cvta.to.shared.u64 t, %1; cvt.u32.u64 %0, t; }" : "=r"(a) : "l"(p));
    return a;
}
__device__ __forceinline__ void mma16816(float* d, const uint32_t* a, const uint32_t* b) {
    asm volatile("mma.sync.aligned.m16n8k16.row.col.f32.bf16.bf16.f32 "
                 "{%0,%1,%2,%3}, {%4,%5,%6,%7}, {%8,%9}, {%0,%1,%2,%3};"
                 : "+f"(d[0]), "+f"(d[1]), "+f"(d[2]), "+f"(d[3])
                 : "r"(a[0]), "r"(a[1]), "r"(a[2]), "r"(a[3]), "r"(b[0]), "r"(b[1]));
}

// ---------------------------------------------------------------------------
__global__ void k_zero() {
    int i = blockIdx.x * 256 + threadIdx.x;
    if (i < Nn * Mm * Dd) g_dw[i] = 0.0f;
    if (i < Nn * Mm)      g_cnt[i] = 0;
    if (i < Nn)           g_emaxbits[i] = 0;
}

// ---------------------------------------------------------------------------
__global__ void k_transpose(const float* __restrict__ x) {
    __shared__ float s[16][65];
    int bn = blockIdx.x;
    int b = bn >> 2, n = bn & 3;
    int t = threadIdx.x;
    const float4* xp = (const float4*)(x + (long long)b * 4096 + n * 1024);
    float4 v = xp[t];
    int d = t >> 2, lb = (t & 3) * 4;
    s[lb + 0][d] = v.x; s[lb + 1][d] = v.y; s[lb + 2][d] = v.z; s[lb + 3][d] = v.w;
    __syncthreads();
    int r = t >> 4, c = t & 15;
    float4 w = make_float4(s[r][c * 4], s[r][c * 4 + 1], s[r][c * 4 + 2], s[r][c * 4 + 3]);
    size_t row = (size_t)n * BL + b * 16 + r;
    ((float4*)g_xt)[row * 16 + c] = w;
    g_xbf[row * 32 + c * 2] =
        (uint32_t)__bfloat16_as_ushort(__float2bfloat16_rn(w.x)) |
        ((uint32_t)__bfloat16_as_ushort(__float2bfloat16_rn(w.y)) << 16);
    g_xbf[row * 32 + c * 2 + 1] =
        (uint32_t)__bfloat16_as_ushort(__float2bfloat16_rn(w.z)) |
        ((uint32_t)__bfloat16_as_ushort(__float2bfloat16_rn(w.w)) << 16);
    if (t < 16) {
        float acc = 0.0f;
        #pragma unroll 8
        for (int dd = 0; dd < 64; dd++) {
            float vv = s[t][dd];
            acc = __fadd_rn(acc, __fmul_rn(vv, vv));
        }
        g_xnorm[(size_t)n * BL + b * 16 + t] = acc;
    }
}

// ---------------------------------------------------------------------------
__global__ void k_enorm(const float* __restrict__ emb) {
    int i = blockIdx.x * blockDim.x + threadIdx.x;   // 0..4095
    const float* e = emb + (size_t)i * 64;
    float s = 0.0f;
    #pragma unroll 8
    for (int d2 = 0; d2 < 32; d2++) {
        float v0 = e[2 * d2], v1 = e[2 * d2 + 1];
        s = __fadd_rn(s, __fmul_rn(v0, v0));
        s = __fadd_rn(s, __fmul_rn(v1, v1));
        g_ebf[(size_t)i * 32 + d2] =
            (uint32_t)__bfloat16_as_ushort(__float2bfloat16_rn(v0)) |
            ((uint32_t)__bfloat16_as_ushort(__float2bfloat16_rn(v1)) << 16);
    }
    g_enorm[i] = s;
    atomicMax(&g_emaxbits[i >> 10], __float_as_int(s));
}

// ---------------------------------------------------------------------------
// HMMA argmin: 256 threads, 128 x-rows/CTA, codes in 4 chunks of 256
// (cp.async double-buffered). Approx bf16 scores -> top-4 slots/thread/row ->
// certified window -> exact reference-bit rescore.
#define SMO_ENS 0                 // 1024 f -> 4096B
#define SMO_XN  4096              // 128 f  -> 512B
#define SMO_A   4608              // 128 rows x 128B = 16384 -> 20992
#define SMO_B   20992             // 2 x 256 x 128B = 65536 -> 86528
#define SM_BYTES 86528

__device__ __forceinline__ float exact_score(int n, int krow, int m,
                                             const float* __restrict__ emb,
                                             float Sx, const float* ens) {
    const float* xr = g_xt + ((size_t)n * BL + krow) * 64;
    const float* er = emb + ((size_t)n * Mm + m) * 64;
    float acc = 0.f;
    #pragma unroll 16
    for (int d = 0; d < 64; d++) acc = __fmaf_rn(xr[d], er[d], acc);
    return __fadd_rn(__fadd_rn(Sx, ens[m]), __fmul_rn(-2.f, acc));
}

__device__ __forceinline__ void upd4(float sa, int m, float* sv, int* si, float& wst) {
    if (sa < wst) {
        if (sv[0] == wst)      { sv[0] = sa; si[0] = m; }
        else if (sv[1] == wst) { sv[1] = sa; si[1] = m; }
        else if (sv[2] == wst) { sv[2] = sa; si[2] = m; }
        else                   { sv[3] = sa; si[3] = m; }
        wst = fmaxf(fmaxf(sv[0], sv[1]), fmaxf(sv[2], sv[3]));
    }
}

extern __shared__ char smx[];
__global__ void __launch_bounds__(256, 2)
k_argmin(const float* __restrict__ emb, float* __restrict__ out) {
    const int n = blockIdx.y;
    const int kbase = blockIdx.x * 128;
    const int t = threadIdx.x;
    const int lane = t & 31, w = t >> 5;
    const int g = lane >> 2, q = lane & 3;
    float* ens = (float*)(smx + SMO_ENS);
    float* xn  = (float*)(smx + SMO_XN);
    uint32_t sb = smem_u32(smx);

    // async fetch B chunks 0 and 1 (each: 256 codes x 128B, swizzled)
    const uint32_t* gB = g_ebf + (size_t)n * Mm * 32;
    #pragma unroll
    for (int i = 0; i < 8; i++) {
        int idx16 = t + i * 256;                       // 16B units
        int row = idx16 >> 3, c16 = idx16 & 7;
        CP_ASYNC16(sb + SMO_B + SWZ((uint32_t)(row * 128 + c16 * 16)),
                   gB + row * 32 + c16 * 4);
    }
    CP_COMMIT();
    #pragma unroll
    for (int i = 0; i < 8; i++) {
        int idx16 = t + i * 256;
        int row = idx16 >> 3, c16 = idx16 & 7;
        CP_ASYNC16(sb + SMO_B + 32768u + SWZ((uint32_t)(row * 128 + c16 * 16)),
                   gB + (256 + row) * 32 + c16 * 4);
    }
    CP_COMMIT();

    // plain loads: ens, xnorm, A tile (swizzled)
    #pragma unroll
    for (int i = 0; i < 4; i++) ens[t + i * 256] = g_enorm[n * Mm + t + i * 256];
    if (t < 128) xn[t] = g_xnorm[(size_t)n * BL + kbase + t];
    {
        const uint32_t* gA = g_xbf + ((size_t)n * BL + kbase) * 32;
        #pragma unroll
        for (int i = 0; i < 16; i++) {
            int idx = t + i * 256;                     // 4B units
            int row = idx >> 5, c4 = idx & 31;
            *(uint32_t*)(smx + SMO_A + SWZ((uint32_t)(row * 128 + c4 * 4))) = gA[idx];
        }
    }
    __syncthreads();

    // A fragments: 4 ksteps, registers for whole sweep
    uint32_t af[4][4];
    const int r0 = w * 16;
    #pragma unroll
    for (int s = 0; s < 4; s++) {
        uint32_t addr = sb + SMO_A +
            SWZ((uint32_t)((r0 + (lane & 15)) * 128 + (2 * s + (lane >> 4)) * 16));
        LDSM4(af[s][0], af[s][1], af[s][2], af[s][3], addr);
    }
    float Sx1 = xn[r0 + g], Sx2 = xn[r0 + 8 + g];
    float emax = sqrtf(__int_as_float(g_emaxbits[n]));

    float sv0[4], sv1[4]; int si0[4], si1[4];
    #pragma unroll
    for (int i = 0; i < 4; i++) { sv0[i] = 3.4e38f; sv1[i] = 3.4e38f; si0[i] = 0; si1[i] = 0; }
    float w0 = 3.4e38f, w1 = 3.4e38f;

    for (int c = 0; c < 4; c++) {
        if (c < 3) { CP_WAIT(1); } else { CP_WAIT(0); }
        __syncthreads();
        uint32_t ub = sb + SMO_B + (uint32_t)((c & 1) * 32768);

        #pragma unroll 2
        for (int mc = 0; mc < 32; mc++) {
            uint32_t bf[8];
            uint32_t a1 = ub + SWZ((uint32_t)((mc * 8 + (lane & 7)) * 128 + (lane >> 3) * 16));
            LDSM4(bf[0], bf[1], bf[2], bf[3], a1);
            uint32_t a2 = ub + SWZ((uint32_t)((mc * 8 + (lane & 7)) * 128 + (4 + (lane >> 3)) * 16));
            LDSM4(bf[4], bf[5], bf[6], bf[7], a2);

            float acc[4] = {0.f, 0.f, 0.f, 0.f};
            mma16816(acc, af[0], bf + 0);
            mma16816(acc, af[1], bf + 2);
            mma16816(acc, af[2], bf + 4);
            mma16816(acc, af[3], bf + 6);

            int n0 = c * 256 + mc * 8;
            float2 en2 = *(float2*)&ens[n0 + q * 2];
            upd4(__fmaf_rn(-2.f, acc[0], en2.x), n0 + q * 2,     sv0, si0, w0);
            upd4(__fmaf_rn(-2.f, acc[1], en2.y), n0 + q * 2 + 1, sv0, si0, w0);
            upd4(__fmaf_rn(-2.f, acc[2], en2.x), n0 + q * 2,     sv1, si1, w1);
            upd4(__fmaf_rn(-2.f, acc[3], en2.y), n0 + q * 2 + 1, sv1, si1, w1);
        }
        __syncthreads();
        if (c < 2) {   // refill freed buffer with chunk c+2
            const uint32_t* gc = gB + (size_t)(c + 2) * 256 * 32;
            uint32_t db = sb + SMO_B + (uint32_t)((c & 1) * 32768);
            #pragma unroll
            for (int i = 0; i < 8; i++) {
                int idx16 = t + i * 256;
                int row = idx16 >> 3, c16 = idx16 & 7;
                CP_ASYNC16(db + SWZ((uint32_t)(row * 128 + c16 * 16)),
                           gc + row * 32 + c16 * 4);
            }
            CP_COMMIT();
        }
    }

    // epilogue: per row certify + exact rescore + quad merge
    #pragma unroll
    for (int r = 0; r < 2; r++) {
        float* sv = r ? sv1 : sv0;
        int*   si = r ? si1 : si0;
        float wst = r ? w1 : w0;
        float Sx  = r ? Sx2 : Sx1;
        int krow = kbase + r0 + r * 8 + g;

        float vmin = fminf(fminf(sv[0], sv[1]), fminf(sv[2], sv[3]));
        vmin = fminf(vmin, __shfl_xor_sync(0xffffffffu, vmin, 1));
        vmin = fminf(vmin, __shfl_xor_sync(0xffffffffu, vmin, 2));
        float thresh = vmin + 0.04f * sqrtf(Sx) * emax + 1e-4f;

        float best = 3.4e38f; int bidx = 0x7fffffff;
        if (wst <= thresh) {
            // overflow: exact scan of this thread's 256 codes (ascending m)
            for (int b8 = 0; b8 < 128; b8++) {
                #pragma unroll
                for (int j = 0; j < 2; j++) {
                    int m = b8 * 8 + q * 2 + j;
                    float sc = exact_score(n, krow, m, emb, Sx, ens);
                    if (sc < best || (sc == best && m < bidx)) { best = sc; bidx = m; }
                }
            }
        } else {
            #pragma unroll
            for (int s = 0; s < 4; s++) {
                if (sv[s] <= thresh) {
                    float sc = exact_score(n, krow, si[s], emb, Sx, ens);
                    if (sc < best || (sc == best && si[s] < bidx)) { best = sc; bidx = si[s]; }
                }
            }
        }
        #pragma unroll
        for (int mk = 1; mk <= 2; mk++) {
            float vo = __shfl_xor_sync(0xffffffffu, best, mk);
            int   io = __shfl_xor_sync(0xffffffffu, bidx, mk);
            if (vo < best || (vo == best && io < bidx)) { best = vo; bidx = io; }
        }
        if (q == 0) {
            g_idx[n * BL + krow] = bidx;
            atomicAdd(&g_cnt[n * Mm + bidx], 1);
            out[OFF_IDX + ((long long)(krow >> 4) * Nn + n) * Ll + (krow & 15)] = (float)bidx;
        }
    }
}

// ---------------------------------------------------------------------------
__global__ void k_dw() {
    int gw = (blockIdx.x * blockDim.x + threadIdx.x) >> 5;
    int lane = threadIdx.x & 31;
    if (gw >= Nn * BL) return;
    int n = gw >> 16;
    int m = g_idx[gw];
    const float* xr = g_xt + (size_t)gw * 64;
    float* dwp = g_dw + ((size_t)n * Mm + m) * 64;
    atomicAdd(dwp + lane,      xr[lane]);
    atomicAdd(dwp + lane + 32, xr[lane + 32]);
}

// ---------------------------------------------------------------------------
__global__ void k_ema(const float* __restrict__ ema_count, float* __restrict__ out) {
    __shared__ float red[1024];
    int t = threadIdx.x;
    float perp = 0.0f;
    for (int n = 0; n < 4; n++) {
        float c = (float)g_cnt[n * Mm + t];
        float raw = DECAYF * ema_count[n * Mm + t] + (1.0f - DECAYF) * c;
        red[t] = raw; __syncthreads();
        for (int s = 512; s > 0; s >>= 1) { if (t < s) red[t] += red[t + s]; __syncthreads(); }
        float nsum = red[0]; __syncthreads();
        float fin = (raw + EPSF) / (nsum + Mm * EPSF) * nsum;
        out[OFF_CNT + n * Mm + t] = fin;
        g_fcnt[n * Mm + t] = fin;
        float avg = c * (1.0f / 65536.0f);
        float term = avg * logf(avg + 1e-10f);
        red[t] = term; __syncthreads();
        for (int s = 512; s > 0; s >>= 1) { if (t < s) red[t] += red[t + s]; __syncthreads(); }
        if (t == 0) perp += expf(-red[0]);
        __syncthreads();
    }
    if (t == 0) out[OFF_PERP] = perp;
}

// ---------------------------------------------------------------------------
__global__ void k_weight(const float* __restrict__ ema_weight, float* __restrict__ out) {
    int i = blockIdx.x * 256 + threadIdx.x;
    float w = DECAYF * ema_weight[i] + (1.0f - DECAYF) * g_dw[i];
    out[OFF_EMW + i] = w;
    out[OFF_EMB + i] = w / g_fcnt[i >> 6];
}

// ---------------------------------------------------------------------------
__global__ void k_gather(const float* __restrict__ x, const float* __restrict__ emb,
                         float* __restrict__ out) {
    __shared__ float se[16][68];
    __shared__ float red[256];
    int bn = blockIdx.x;
    int b = bn >> 2, n = bn & 3;
    int t = threadIdx.x;
    int r = t >> 4, c = t & 15;
    int idx = g_idx[n * BL + b * 16 + r];
    const float4* ep = (const float4*)emb + ((size_t)n * Mm + idx) * 16;
    float4 v = ep[c];
    se[r][c * 4] = v.x; se[r][c * 4 + 1] = v.y; se[r][c * 4 + 2] = v.z; se[r][c * 4 + 3] = v.w;
    __syncthreads();
    long long base = (long long)b * 4096 + n * 1024;
    float4 xv = ((const float4*)(x + base))[t];
    int lin = t * 4;
    int d = lin >> 4, l0 = lin & 15;
    float q0 = se[l0 + 0][d], q1 = se[l0 + 1][d], q2 = se[l0 + 2][d], q3 = se[l0 + 3][d];
    ((float4*)(out + OFF_ZQ + base))[t] = make_float4(q0, q1, q2, q3);
    float2* ez = (float2*)(out + OFF_EZQ + base);
    ez[2 * t]     = make_float2(q0, q1);
    ez[2 * t + 1] = make_float2(q2, q3);
    float d0 = xv.x - q0, d1 = xv.y - q1, d2 = xv.z - q2, d3 = xv.w - q3;
    red[t] = d0 * d0 + d1 * d1 + d2 * d2 + d3 * d3;
    __syncthreads();
    for (int s = 128; s > 0; s >>= 1) { if (t < s) red[t] += red[t + s]; __syncthreads(); }
    if (t == 0) g_losspart[bn] = red[0];
}

// ---------------------------------------------------------------------------
__global__ void k_loss(float* __restrict__ out) {
    __shared__ float red[1024];
    int t = threadIdx.x;
    float s = 0.0f;
    for (int i = t; i < Bb * Nn; i += 1024) s += g_losspart[i];
    red[t] = s; __syncthreads();
    for (int st = 512; st > 0; st >>= 1) { if (t < st) red[t] += red[t + st]; __syncthreads(); }
    if (t == 0) out[OFF_LOSS] = COMMITF * red[0] / 16777216.0f;
}

// ---------------------------------------------------------------------------
extern "C" void kernel_launch(void* const* d_in, const int* in_sizes, int n_in,
                              void* d_out, int out_size) {
    const float* x          = (const float*)d_in[0];
    const float* emb        = (const float*)d_in[1];
    const float* ema_count  = (const float*)d_in[2];
    const float* ema_weight = (const float*)d_in[3];
    float* out = (float*)d_out;

    cudaFuncSetAttribute(k_argmin, cudaFuncAttributeMaxDynamicSharedMemorySize, SM_BYTES);

    k_zero<<<1024, 256>>>();
    k_transpose<<<Bb * Nn, 256>>>(x);
    k_enorm<<<16, 256>>>(emb);
    dim3 ga(BL / 128, Nn);
    k_argmin<<<ga, 256, SM_BYTES>>>(emb, out);
    k_dw<<<(Nn * BL) / 8, 256>>>();
    k_ema<<<1, 1024>>>(ema_count, out);
    k_weight<<<1024, 256>>>(ema_weight, out);
    k_gather<<<Bb * Nn, 256>>>(x, emb, out);
    k_loss<<<1, 1024>>>(out);
}

// round 9
// speedup vs baseline: 1.3723x; 1.3723x over previous
#include <cuda_runtime.h>
#include <cuda_bf16.h>
#include <cstdint>

#define Nn 4
#define Mm 1024
#define Dd 64
#define Ll 16
#define Bb 4096
#define BL 65536
#define DECAYF 0.999f
#define EPSF 1e-5f
#define COMMITF 0.05f

#define OFF_ZQ   0LL
#define OFF_LOSS 16777216LL
#define OFF_PERP 16777217LL
#define OFF_IDX  16777218LL
#define OFF_EZQ  17039362LL
#define OFF_EMB  33816578LL
#define OFF_CNT  34078722LL
#define OFF_EMW  34082818LL

__device__ float    g_xt[Nn * BL * Dd];
__device__ uint32_t g_xbf[Nn * BL * 32];    // x bf16 pairs, 128B per row
__device__ uint32_t g_ebf[Nn * Mm * 32];    // embedding bf16 pairs, 128B per row
__device__ float    g_xnorm[Nn * BL];
__device__ int      g_idx[Nn * BL];
__device__ float    g_dw[Nn * Mm * Dd];
__device__ int      g_cnt[Nn * Mm];
__device__ float    g_enorm[Nn * Mm];
__device__ int      g_emaxbits[Nn];
__device__ float    g_fcnt[Nn * Mm];
__device__ float    g_losspart[Bb * Nn];

#define SWZ(off) ((off) ^ (((off) >> 3) & 0x70))
#define CP_ASYNC16(dst, src) \
    asm volatile("cp.async.cg.shared.global [%0], [%1], 16;" :: "r"(dst), "l"(src))
#define CP_COMMIT() asm volatile("cp.async.commit_group;" ::: "memory")
#define CP_WAIT(nconst) asm volatile("cp.async.wait_group %0;" :: "n"(nconst) : "memory")
#define LDSM4(r0, r1, r2, r3, addr) \
    asm volatile("ldmatrix.sync.aligned.m8n8.x4.shared.b16 {%0,%1,%2,%3}, [%4];" \
                 : "=r"(r0), "=r"(r1), "=r"(r2), "=r"(r3) : "r"(addr))

__device__ __forceinline__ uint32_t smem_u32(const void* p) {
    uint32_t a;
    asm("{ .reg .u64 t; cvta.to.shared.u64 t, %1; cvt.u32.u64 %0, t; }" : "=r"(a) : "l"(p));
    return a;
}
__device__ __forceinline__ void mma16816(float* d, const uint32_t* a, const uint32_t* b) {
    asm volatile("mma.sync.aligned.m16n8k16.row.col.f32.bf16.bf16.f32 "
                 "{%0,%1,%2,%3}, {%4,%5,%6,%7}, {%8,%9}, {%0,%1,%2,%3};"
                 : "+f"(d[0]), "+f"(d[1]), "+f"(d[2]), "+f"(d[3])
                 : "r"(a[0]), "r"(a[1]), "r"(a[2]), "r"(a[3]), "r"(b[0]), "r"(b[1]));
}

// ---------------------------------------------------------------------------
__global__ void k_zero() {
    int i = blockIdx.x * 256 + threadIdx.x;
    if (i < Nn * Mm * Dd) g_dw[i] = 0.0f;
    if (i < Nn * Mm)      g_cnt[i] = 0;
    if (i < Nn)           g_emaxbits[i] = 0;
}

// ---------------------------------------------------------------------------
__global__ void k_transpose(const float* __restrict__ x) {
    __shared__ float s[16][65];
    int bn = blockIdx.x;
    int b = bn >> 2, n = bn & 3;
    int t = threadIdx.x;
    const float4* xp = (const float4*)(x + (long long)b * 4096 + n * 1024);
    float4 v = xp[t];
    int d = t >> 2, lb = (t & 3) * 4;
    s[lb + 0][d] = v.x; s[lb + 1][d] = v.y; s[lb + 2][d] = v.z; s[lb + 3][d] = v.w;
    __syncthreads();
    int r = t >> 4, c = t & 15;
    float4 w = make_float4(s[r][c * 4], s[r][c * 4 + 1], s[r][c * 4 + 2], s[r][c * 4 + 3]);
    size_t row = (size_t)n * BL + b * 16 + r;
    ((float4*)g_xt)[row * 16 + c] = w;
    g_xbf[row * 32 + c * 2] =
        (uint32_t)__bfloat16_as_ushort(__float2bfloat16_rn(w.x)) |
        ((uint32_t)__bfloat16_as_ushort(__float2bfloat16_rn(w.y)) << 16);
    g_xbf[row * 32 + c * 2 + 1] =
        (uint32_t)__bfloat16_as_ushort(__float2bfloat16_rn(w.z)) |
        ((uint32_t)__bfloat16_as_ushort(__float2bfloat16_rn(w.w)) << 16);
    if (t < 16) {
        float acc = 0.0f;
        #pragma unroll 8
        for (int dd = 0; dd < 64; dd++) {
            float vv = s[t][dd];
            acc = __fadd_rn(acc, __fmul_rn(vv, vv));
        }
        g_xnorm[(size_t)n * BL + b * 16 + t] = acc;
    }
}

// ---------------------------------------------------------------------------
__global__ void k_enorm(const float* __restrict__ emb) {
    int i = blockIdx.x * blockDim.x + threadIdx.x;   // 0..4095
    const float* e = emb + (size_t)i * 64;
    float s = 0.0f;
    #pragma unroll 8
    for (int d2 = 0; d2 < 32; d2++) {
        float v0 = e[2 * d2], v1 = e[2 * d2 + 1];
        s = __fadd_rn(s, __fmul_rn(v0, v0));
        s = __fadd_rn(s, __fmul_rn(v1, v1));
        g_ebf[(size_t)i * 32 + d2] =
            (uint32_t)__bfloat16_as_ushort(__float2bfloat16_rn(v0)) |
            ((uint32_t)__bfloat16_as_ushort(__float2bfloat16_rn(v1)) << 16);
    }
    g_enorm[i] = s;
    atomicMax(&g_emaxbits[i >> 10], __float_as_int(s));
}

// ---------------------------------------------------------------------------
// HMMA argmin with branchless top-4 tracking + unique-candidate shortcut.
// 256 threads, 128 rows/CTA, 8 chunks of 128 codes (cp.async double-buffered).
#define SMO_ENS 0                 // 1024 f = 4096B
#define SMO_XN  4096              // 128 f  = 512B
#define SMO_A   4608              // 128 x 128B = 16384 -> 20992
#define SMO_B   20992             // 2 x 128 x 128B = 32768 -> 53760
#define SM_BYTES 53760

__device__ __forceinline__ float exact_score(int n, int krow, int m,
                                             const float* __restrict__ emb,
                                             float Sx, const float* ens) {
    const float* xr = g_xt + ((size_t)n * BL + krow) * 64;
    const float* er = emb + ((size_t)n * Mm + m) * 64;
    float acc = 0.f;
    #pragma unroll 16
    for (int d = 0; d < 64; d++) acc = __fmaf_rn(xr[d], er[d], acc);
    return __fadd_rn(__fadd_rn(Sx, ens[m]), __fmul_rn(-2.f, acc));
}

struct Top4 { float m1, m2, m3, m4; int i1, i2, i3; };

__device__ __forceinline__ void t4_init(Top4& t) {
    t.m1 = t.m2 = t.m3 = t.m4 = 3.4e38f; t.i1 = t.i2 = t.i3 = 0;
}
__device__ __forceinline__ void t4_upd(Top4& t, float s, int idx) {
    if (s < t.m4) {
        bool b1 = s < t.m1, b2 = s < t.m2, b3 = s < t.m3;
        t.m4 = b3 ? t.m3 : s;
        t.m3 = b3 ? (b2 ? t.m2 : s) : t.m3;
        t.i3 = b3 ? (b2 ? t.i2 : idx) : t.i3;
        t.m2 = b2 ? (b1 ? t.m1 : s) : t.m2;
        t.i2 = b2 ? (b1 ? t.i1 : idx) : t.i2;
        t.m1 = b1 ? s : t.m1;
        t.i1 = b1 ? idx : t.i1;
    }
}

extern __shared__ char smx[];
__global__ void __launch_bounds__(256, 3)
k_argmin(const float* __restrict__ emb, float* __restrict__ out) {
    const int n = blockIdx.y;
    const int kbase = blockIdx.x * 128;
    const int t = threadIdx.x;
    const int lane = t & 31, w = t >> 5;
    const int g = lane >> 2, q = lane & 3;
    float* ens = (float*)(smx + SMO_ENS);
    float* xn  = (float*)(smx + SMO_XN);
    uint32_t sb = smem_u32(smx);

    // async fetch B chunks 0,1 (each 128 codes x 128B, swizzled)
    const uint32_t* gB = g_ebf + (size_t)n * Mm * 32;
    #pragma unroll
    for (int cc = 0; cc < 2; cc++) {
        #pragma unroll
        for (int i = 0; i < 4; i++) {
            int idx16 = t + i * 256;                   // 0..1023 16B-units
            int row = idx16 >> 3, c16 = idx16 & 7;
            CP_ASYNC16(sb + SMO_B + (uint32_t)(cc * 16384) +
                       SWZ((uint32_t)(row * 128 + c16 * 16)),
                       gB + (cc * 128 + row) * 32 + c16 * 4);
        }
        CP_COMMIT();
    }

    // plain loads: ens, xnorm, A tile (swizzled)
    #pragma unroll
    for (int i = 0; i < 4; i++) ens[t + i * 256] = g_enorm[n * Mm + t + i * 256];
    if (t < 128) xn[t] = g_xnorm[(size_t)n * BL + kbase + t];
    {
        const uint32_t* gA = g_xbf + ((size_t)n * BL + kbase) * 32;
        #pragma unroll
        for (int i = 0; i < 16; i++) {
            int idx = t + i * 256;                     // 4B units
            int row = idx >> 5, c4 = idx & 31;
            *(uint32_t*)(smx + SMO_A + SWZ((uint32_t)(row * 128 + c4 * 4))) = gA[idx];
        }
    }
    __syncthreads();

    // A fragments (registers for entire sweep)
    uint32_t af[4][4];
    const int r0 = w * 16;
    #pragma unroll
    for (int s = 0; s < 4; s++) {
        uint32_t addr = sb + SMO_A +
            SWZ((uint32_t)((r0 + (lane & 15)) * 128 + (2 * s + (lane >> 4)) * 16));
        LDSM4(af[s][0], af[s][1], af[s][2], af[s][3], addr);
    }
    float Sx1 = xn[r0 + g], Sx2 = xn[r0 + 8 + g];
    float emax = sqrtf(__int_as_float(g_emaxbits[n]));

    Top4 ta, tb;
    t4_init(ta); t4_init(tb);

    for (int c = 0; c < 8; c++) {
        if (c < 7) { CP_WAIT(1); } else { CP_WAIT(0); }
        __syncthreads();
        uint32_t ub = sb + SMO_B + (uint32_t)((c & 1) * 16384);

        #pragma unroll 2
        for (int mc = 0; mc < 16; mc++) {
            uint32_t bf[8];
            uint32_t a1 = ub + SWZ((uint32_t)((mc * 8 + (lane & 7)) * 128 + (lane >> 3) * 16));
            LDSM4(bf[0], bf[1], bf[2], bf[3], a1);
            uint32_t a2 = ub + SWZ((uint32_t)((mc * 8 + (lane & 7)) * 128 + (4 + (lane >> 3)) * 16));
            LDSM4(bf[4], bf[5], bf[6], bf[7], a2);

            float acc[4] = {0.f, 0.f, 0.f, 0.f};
            mma16816(acc, af[0], bf + 0);
            mma16816(acc, af[1], bf + 2);
            mma16816(acc, af[2], bf + 4);
            mma16816(acc, af[3], bf + 6);

            int n0 = c * 128 + mc * 8;
            float2 en2 = *(float2*)&ens[n0 + q * 2];
            t4_upd(ta, __fmaf_rn(-2.f, acc[0], en2.x), n0 + q * 2);
            t4_upd(ta, __fmaf_rn(-2.f, acc[1], en2.y), n0 + q * 2 + 1);
            t4_upd(tb, __fmaf_rn(-2.f, acc[2], en2.x), n0 + q * 2);
            t4_upd(tb, __fmaf_rn(-2.f, acc[3], en2.y), n0 + q * 2 + 1);
        }
        __syncthreads();
        if (c < 6) {   // refill freed buffer with chunk c+2
            const uint32_t* gc = gB + (size_t)(c + 2) * 128 * 32;
            uint32_t db = sb + SMO_B + (uint32_t)((c & 1) * 16384);
            #pragma unroll
            for (int i = 0; i < 4; i++) {
                int idx16 = t + i * 256;
                int row = idx16 >> 3, c16 = idx16 & 7;
                CP_ASYNC16(db + SWZ((uint32_t)(row * 128 + c16 * 16)),
                           gc + row * 32 + c16 * 4);
            }
            CP_COMMIT();
        }
    }

    // ---- epilogue: certify; unique -> direct; else exact rescore ----------
    #pragma unroll
    for (int r = 0; r < 2; r++) {
        Top4& tk = r ? tb : ta;
        float Sx = r ? Sx2 : Sx1;
        int krow = kbase + r0 + r * 8 + g;

        float vmin = tk.m1;
        vmin = fminf(vmin, __shfl_xor_sync(0xffffffffu, vmin, 1));
        vmin = fminf(vmin, __shfl_xor_sync(0xffffffffu, vmin, 2));
        float thr = vmin + 0.04f * sqrtf(Sx) * emax + 1e-4f;

        int cl = (tk.m1 <= thr) + (tk.m2 <= thr) + (tk.m3 <= thr);
        int ofl = (tk.m4 <= thr) ? 1 : 0;
        int ct = cl + __shfl_xor_sync(0xffffffffu, cl, 1);
        ct += __shfl_xor_sync(0xffffffffu, ct, 2);
        int oq = ofl + __shfl_xor_sync(0xffffffffu, ofl, 1);
        oq += __shfl_xor_sync(0xffffffffu, oq, 2);

        int bidx;
        if (ct == 1 && oq == 0) {
            // unique certified candidate == exact argmin; no rescore needed
            int ci = (tk.m1 <= thr) ? tk.i1 : 0x7fffffff;
            ci = min(ci, __shfl_xor_sync(0xffffffffu, ci, 1));
            ci = min(ci, __shfl_xor_sync(0xffffffffu, ci, 2));
            bidx = ci;
        } else {
            float best = 3.4e38f; bidx = 0x7fffffff;
            if (ofl) {
                // thread may have >4 in-window codes: exact scan of its 256
                for (int b8 = 0; b8 < 128; b8++) {
                    #pragma unroll
                    for (int j = 0; j < 2; j++) {
                        int m = b8 * 8 + q * 2 + j;
                        float sc = exact_score(n, krow, m, emb, Sx, ens);
                        if (sc < best || (sc == best && m < bidx)) { best = sc; bidx = m; }
                    }
                }
            } else {
                if (tk.m1 <= thr) {
                    float sc = exact_score(n, krow, tk.i1, emb, Sx, ens);
                    if (sc < best || (sc == best && tk.i1 < bidx)) { best = sc; bidx = tk.i1; }
                }
                if (tk.m2 <= thr) {
                    float sc = exact_score(n, krow, tk.i2, emb, Sx, ens);
                    if (sc < best || (sc == best && tk.i2 < bidx)) { best = sc; bidx = tk.i2; }
                }
                if (tk.m3 <= thr) {
                    float sc = exact_score(n, krow, tk.i3, emb, Sx, ens);
                    if (sc < best || (sc == best && tk.i3 < bidx)) { best = sc; bidx = tk.i3; }
                }
            }
            #pragma unroll
            for (int mk = 1; mk <= 2; mk++) {
                float vo = __shfl_xor_sync(0xffffffffu, best, mk);
                int   io = __shfl_xor_sync(0xffffffffu, bidx, mk);
                if (vo < best || (vo == best && io < bidx)) { best = vo; bidx = io; }
            }
        }
        if (q == 0) {
            g_idx[n * BL + krow] = bidx;
            atomicAdd(&g_cnt[n * Mm + bidx], 1);
            out[OFF_IDX + ((long long)(krow >> 4) * Nn + n) * Ll + (krow & 15)] = (float)bidx;
        }
    }
}

// ---------------------------------------------------------------------------
__global__ void k_dw() {
    int gw = (blockIdx.x * blockDim.x + threadIdx.x) >> 5;
    int lane = threadIdx.x & 31;
    if (gw >= Nn * BL) return;
    int n = gw >> 16;
    int m = g_idx[gw];
    const float* xr = g_xt + (size_t)gw * 64;
    float* dwp = g_dw + ((size_t)n * Mm + m) * 64;
    atomicAdd(dwp + lane,      xr[lane]);
    atomicAdd(dwp + lane + 32, xr[lane + 32]);
}

// ---------------------------------------------------------------------------
__global__ void k_ema(const float* __restrict__ ema_count, float* __restrict__ out) {
    __shared__ float red[1024];
    int t = threadIdx.x;
    float perp = 0.0f;
    for (int n = 0; n < 4; n++) {
        float c = (float)g_cnt[n * Mm + t];
        float raw = DECAYF * ema_count[n * Mm + t] + (1.0f - DECAYF) * c;
        red[t] = raw; __syncthreads();
        for (int s = 512; s > 0; s >>= 1) { if (t < s) red[t] += red[t + s]; __syncthreads(); }
        float nsum = red[0]; __syncthreads();
        float fin = (raw + EPSF) / (nsum + Mm * EPSF) * nsum;
        out[OFF_CNT + n * Mm + t] = fin;
        g_fcnt[n * Mm + t] = fin;
        float avg = c * (1.0f / 65536.0f);
        float term = avg * logf(avg + 1e-10f);
        red[t] = term; __syncthreads();
        for (int s = 512; s > 0; s >>= 1) { if (t < s) red[t] += red[t + s]; __syncthreads(); }
        if (t == 0) perp += expf(-red[0]);
        __syncthreads();
    }
    if (t == 0) out[OFF_PERP] = perp;
}

// ---------------------------------------------------------------------------
__global__ void k_weight(const float* __restrict__ ema_weight, float* __restrict__ out) {
    int i = blockIdx.x * 256 + threadIdx.x;
    float w = DECAYF * ema_weight[i] + (1.0f - DECAYF) * g_dw[i];
    out[OFF_EMW + i] = w;
    out[OFF_EMB + i] = w / g_fcnt[i >> 6];
}

// ---------------------------------------------------------------------------
__global__ void k_gather(const float* __restrict__ x, const float* __restrict__ emb,
                         float* __restrict__ out) {
    __shared__ float se[16][68];
    __shared__ float red[256];
    int bn = blockIdx.x;
    int b = bn >> 2, n = bn & 3;
    int t = threadIdx.x;
    int r = t >> 4, c = t & 15;
    int idx = g_idx[n * BL + b * 16 + r];
    const float4* ep = (const float4*)emb + ((size_t)n * Mm + idx) * 16;
    float4 v = ep[c];
    se[r][c * 4] = v.x; se[r][c * 4 + 1] = v.y; se[r][c * 4 + 2] = v.z; se[r][c * 4 + 3] = v.w;
    __syncthreads();
    long long base = (long long)b * 4096 + n * 1024;
    float4 xv = ((const float4*)(x + base))[t];
    int lin = t * 4;
    int d = lin >> 4, l0 = lin & 15;
    float q0 = se[l0 + 0][d], q1 = se[l0 + 1][d], q2 = se[l0 + 2][d], q3 = se[l0 + 3][d];
    ((float4*)(out + OFF_ZQ + base))[t] = make_float4(q0, q1, q2, q3);
    float2* ez = (float2*)(out + OFF_EZQ + base);
    ez[2 * t]     = make_float2(q0, q1);
    ez[2 * t + 1] = make_float2(q2, q3);
    float d0 = xv.x - q0, d1 = xv.y - q1, d2 = xv.z - q2, d3 = xv.w - q3;
    red[t] = d0 * d0 + d1 * d1 + d2 * d2 + d3 * d3;
    __syncthreads();
    for (int s = 128; s > 0; s >>= 1) { if (t < s) red[t] += red[t + s]; __syncthreads(); }
    if (t == 0) g_losspart[bn] = red[0];
}

// ---------------------------------------------------------------------------
__global__ void k_loss(float* __restrict__ out) {
    __shared__ float red[1024];
    int t = threadIdx.x;
    float s = 0.0f;
    for (int i = t; i < Bb * Nn; i += 1024) s += g_losspart[i];
    red[t] = s; __syncthreads();
    for (int st = 512; st > 0; st >>= 1) { if (t < st) red[t] += red[t + st]; __syncthreads(); }
    if (t == 0) out[OFF_LOSS] = COMMITF * red[0] / 16777216.0f;
}

// ---------------------------------------------------------------------------
extern "C" void kernel_launch(void* const* d_in, const int* in_sizes, int n_in,
                              void* d_out, int out_size) {
    const float* x          = (const float*)d_in[0];
    const float* emb        = (const float*)d_in[1];
    const float* ema_count  = (const float*)d_in[2];
    const float* ema_weight = (const float*)d_in[3];
    float* out = (float*)d_out;

    cudaFuncSetAttribute(k_argmin, cudaFuncAttributeMaxDynamicSharedMemorySize, SM_BYTES);

    k_zero<<<1024, 256>>>();
    k_transpose<<<Bb * Nn, 256>>>(x);
    k_enorm<<<16, 256>>>(emb);
    dim3 ga(BL / 128, Nn);
    k_argmin<<<ga, 256, SM_BYTES>>>(emb, out);
    k_dw<<<(Nn * BL) / 8, 256>>>();
    k_ema<<<1, 1024>>>(ema_count, out);
    k_weight<<<1024, 256>>>(ema_weight, out);
    k_gather<<<Bb * Nn, 256>>>(x, emb, out);
    k_loss<<<1, 1024>>>(out);
}

// round 10
// speedup vs baseline: 2.2965x; 1.6735x over previous
#include <cuda_runtime.h>
#include <cstdint>

#define Nn 4
#define Mm 1024
#define Dd 64
#define Ll 16
#define Bb 4096
#define BL 65536
#define DECAYF 0.999f
#define EPSF 1e-5f
#define COMMITF 0.05f

#define OFF_ZQ   0LL
#define OFF_LOSS 16777216LL
#define OFF_PERP 16777217LL
#define OFF_IDX  16777218LL
#define OFF_EZQ  17039362LL
#define OFF_EMB  33816578LL
#define OFF_CNT  34078722LL
#define OFF_EMW  34082818LL

__device__ float g_xt[Nn * BL * Dd];      // x (n, k, d) row-major
__device__ float g_xtT[Nn * Dd * BL];     // x transposed (n, d, k)
__device__ float g_etT[Nn * Dd * Mm];     // embedding transposed (n, d, m)
__device__ float g_xnorm[Nn * BL];
__device__ int   g_idx[Nn * BL];
__device__ float g_dw[Nn * Mm * Dd];
__device__ int   g_cnt[Nn * Mm];
__device__ float g_enorm[Nn * Mm];
__device__ float g_fcnt[Nn * Mm];
__device__ float g_losspart[Bb * Nn];

#define CP_ASYNC16(dst, src) \
    asm volatile("cp.async.cg.shared.global [%0], [%1], 16;" :: "r"(dst), "l"(src))
#define CP_COMMIT() asm volatile("cp.async.commit_group;" ::: "memory")
#define CP_WAIT0() asm volatile("cp.async.wait_group 0;" ::: "memory")

// packed dual-fp32 FMA (each lane IEEE fp32 -> bit-exact per-element chain)
#define FMA2(acc, a, b) \
    asm("fma.rn.f32x2 %0, %1, %2, %0;" : "+l"(acc) : "l"(a), "l"(b))
#define DUP2(dst, f) \
    asm("mov.b64 %0, {%1, %1};" : "=l"(dst) : "r"(__float_as_uint(f)))

__device__ __forceinline__ uint32_t smem_u32(const void* p) {
    uint32_t a;
    asm("{ .reg .u64 t; cvta.to.shared.u64 t, %1; cvt.u32.u64 %0, t; }" : "=r"(a) : "l"(p));
    return a;
}

// ---------------------------------------------------------------------------
__global__ void k_zero() {
    int i = blockIdx.x * 256 + threadIdx.x;
    if (i < Nn * Mm * Dd) g_dw[i] = 0.0f;
    if (i < Nn * Mm)      g_cnt[i] = 0;
}

// ---------------------------------------------------------------------------
// Transpose x -> g_xt (row-major) + g_xtT (d-major); ||x||^2 reference-rounded.
__global__ void k_transpose(const float* __restrict__ x) {
    __shared__ float s[16][65];
    int bn = blockIdx.x;
    int b = bn >> 2, n = bn & 3;
    int t = threadIdx.x;
    const float4* xp = (const float4*)(x + (long long)b * 4096 + n * 1024);
    float4 v = xp[t];
    int d = t >> 2, lb = (t & 3) * 4;
    s[lb + 0][d] = v.x; s[lb + 1][d] = v.y; s[lb + 2][d] = v.z; s[lb + 3][d] = v.w;
    __syncthreads();
    int r = t >> 4, c = t & 15;
    float4 w = make_float4(s[r][c * 4], s[r][c * 4 + 1], s[r][c * 4 + 2], s[r][c * 4 + 3]);
    size_t row = (size_t)n * BL + b * 16 + r;
    ((float4*)g_xt)[row * 16 + c] = w;
    // transposed: thread covers d = t>>2, 4 k-locals
    int dd = t >> 2, l4 = (t & 3) * 4;
    size_t tb = ((size_t)n * 64 + dd) * BL + b * 16 + l4;
    g_xtT[tb + 0] = s[l4 + 0][dd];
    g_xtT[tb + 1] = s[l4 + 1][dd];
    g_xtT[tb + 2] = s[l4 + 2][dd];
    g_xtT[tb + 3] = s[l4 + 3][dd];
    if (t < 16) {
        float acc = 0.0f;
        #pragma unroll 8
        for (int d2 = 0; d2 < 64; d2++) {
            float vv = s[t][d2];
            acc = __fadd_rn(acc, __fmul_rn(vv, vv));
        }
        g_xnorm[(size_t)n * BL + b * 16 + t] = acc;
    }
}

// ---------------------------------------------------------------------------
__global__ void k_enorm(const float* __restrict__ emb) {
    int i = blockIdx.x * blockDim.x + threadIdx.x;   // 0..4095
    const float* e = emb + (size_t)i * 64;
    float s = 0.0f;
    #pragma unroll 8
    for (int d = 0; d < 64; d++) {
        float v = e[d];
        s = __fadd_rn(s, __fmul_rn(v, v));
    }
    g_enorm[i] = s;
}

// ---------------------------------------------------------------------------
// Embedding transpose: g_etT[n][d][m]. grid (16, 4), 256 thr, 64m x 64d tile.
__global__ void k_et(const float* __restrict__ emb) {
    __shared__ float sm[64][65];
    int n = blockIdx.y, mbase = blockIdx.x * 64;
    int t = threadIdx.x;
    #pragma unroll
    for (int i = 0; i < 16; i++) {
        int idx = t + i * 256;               // m = idx>>6, d = idx&63
        sm[idx >> 6][idx & 63] = emb[((size_t)n * Mm + mbase + (idx >> 6)) * 64 + (idx & 63)];
    }
    __syncthreads();
    #pragma unroll
    for (int i = 0; i < 16; i++) {
        int idx = t + i * 256;               // d = idx>>6, m = idx&63
        g_etT[((size_t)n * 64 + (idx >> 6)) * Mm + mbase + (idx & 63)] = sm[idx & 63][idx >> 6];
    }
}

// ---------------------------------------------------------------------------
// FFMA2 argmin. 256 threads (tx=t&31, ty=t>>5). CTA: 128 k-rows, 8 m-tiles of
// 128. Thread: TK=16 (8 f32x2 k-pairs) x TM=4 consecutive m. Bit-exact scores.
#define KST 132
#define SMO_ENS 0            // 1024 f
#define SMO_XNR 1024         // 128 f
#define SMO_XT  1152         // 64*132 = 8448 f
#define SMO_EST 9600         // 8448 f
#define SMO_KEY 18048        // 4096 ull = 8192 f
#define SM_BYTES (26240 * 4) // 104960

extern __shared__ float smf[];
__global__ void __launch_bounds__(256, 2)
k_argmin(float* __restrict__ out) {
    const int n = blockIdx.y;
    const int kbase = blockIdx.x * 128;
    const int t = threadIdx.x;
    const int tx = t & 31, ty = t >> 5;
    float* ens = smf + SMO_ENS;
    float* xnr = smf + SMO_XNR;
    float* xt  = smf + SMO_XT;
    float* est = smf + SMO_EST;
    unsigned long long* keys = (unsigned long long*)(smf + SMO_KEY);
    uint32_t sb = smem_u32(smf);

    const float* gx = g_xtT + (size_t)n * 64 * BL;
    const float* ge = g_etT + (size_t)n * 64 * Mm;

    // async: xt tile (64 d x 128 k) + est tile 0 (64 d x 128 m)
    #pragma unroll
    for (int i = 0; i < 8; i++) {
        int idx = t + i * 256;               // 2048 16B-chunks: row=idx>>5, c=idx&31
        int row = idx >> 5, c = idx & 31;
        CP_ASYNC16(sb + (uint32_t)((SMO_XT + row * KST + c * 4) * 4),
                   gx + (size_t)row * BL + kbase + c * 4);
    }
    #pragma unroll
    for (int i = 0; i < 8; i++) {
        int idx = t + i * 256;
        int row = idx >> 5, c = idx & 31;
        CP_ASYNC16(sb + (uint32_t)((SMO_EST + row * KST + c * 4) * 4),
                   ge + (size_t)row * Mm + c * 4);
    }
    CP_COMMIT();

    #pragma unroll
    for (int i = 0; i < 4; i++) ens[t + i * 256] = g_enorm[n * Mm + t + i * 256];
    if (t < 128) xnr[t] = g_xnorm[(size_t)n * BL + kbase + t];
    #pragma unroll
    for (int i = 0; i < 16; i++)
        keys[(ty * 16 + i) * 32 + tx] = 0xFFFFFFFFFFFFFFFFULL;

    CP_WAIT0();
    __syncthreads();

    for (int mt = 0; mt < 8; mt++) {
        const int mbase = mt * 128;

        unsigned long long acc[8][4];
        #pragma unroll
        for (int p = 0; p < 8; p++)
            #pragma unroll
            for (int j = 0; j < 4; j++) acc[p][j] = 0ULL;

        #pragma unroll 2
        for (int d = 0; d < 64; d++) {
            const ulonglong2* xr = (const ulonglong2*)&xt[d * KST + ty * 16];
            ulonglong2 xa = xr[0], xb = xr[1], xc = xr[2], xd_ = xr[3];
            unsigned long long xp[8] = {xa.x, xa.y, xb.x, xb.y, xc.x, xc.y, xd_.x, xd_.y};
            float4 e4 = *(const float4*)&est[d * KST + tx * 4];
            unsigned long long ee[4];
            DUP2(ee[0], e4.x); DUP2(ee[1], e4.y); DUP2(ee[2], e4.z); DUP2(ee[3], e4.w);
            #pragma unroll
            for (int p = 0; p < 8; p++)
                #pragma unroll
                for (int j = 0; j < 4; j++)
                    FMA2(acc[p][j], xp[p], ee[j]);
        }

        // fold: per k-row, min over this thread's 4 m (ascending m, '<' keeps
        // lowest) using the reference-exact score, then merge into key slot.
        float4 se4 = *(const float4*)&ens[mbase + tx * 4];
        float se[4] = {se4.x, se4.y, se4.z, se4.w};
        #pragma unroll
        for (int p = 0; p < 8; p++) {
            #pragma unroll
            for (int h = 0; h < 2; h++) {
                int krow = ty * 16 + p * 2 + h;
                float Sx = xnr[krow];
                float bestv = 3.4e38f; int bestm = 0;
                #pragma unroll
                for (int j = 0; j < 4; j++) {
                    uint32_t bits = h ? (uint32_t)(acc[p][j] >> 32) : (uint32_t)acc[p][j];
                    float dot = __uint_as_float(bits);
                    float sc = __fadd_rn(__fadd_rn(Sx, se[j]), __fmul_rn(-2.0f, dot));
                    if (sc < bestv) { bestv = sc; bestm = mbase + tx * 4 + j; }
                }
                uint32_t b = __float_as_uint(bestv);
                b ^= (b & 0x80000000u) ? 0xFFFFFFFFu : 0x80000000u;
                unsigned long long key = ((unsigned long long)b << 32) | (uint32_t)bestm;
                unsigned long long* kp = &keys[krow * 32 + tx];
                if (key < *kp) *kp = key;
            }
        }
        __syncthreads();
        if (mt < 7) {
            #pragma unroll
            for (int i = 0; i < 8; i++) {
                int idx = t + i * 256;
                int row = idx >> 5, c = idx & 31;
                CP_ASYNC16(sb + (uint32_t)((SMO_EST + row * KST + c * 4) * 4),
                           ge + (size_t)row * Mm + (mt + 1) * 128 + c * 4);
            }
            CP_COMMIT();
            CP_WAIT0();
            __syncthreads();
        }
    }

    // final: reduce 32 tx-slots per row (key64 min = exact argmin, tie->low m)
    if (t < 128) {
        unsigned long long best = keys[t * 32];
        #pragma unroll 8
        for (int q = 1; q < 32; q++) {
            unsigned long long v = keys[t * 32 + q];
            if (v < best) best = v;
        }
        int bidx = (int)(uint32_t)best;
        int kg = kbase + t;
        g_idx[n * BL + kg] = bidx;
        atomicAdd(&g_cnt[n * Mm + bidx], 1);
        out[OFF_IDX + ((long long)(kg >> 4) * Nn + n) * Ll + (kg & 15)] = (float)bidx;
    }
}

// ---------------------------------------------------------------------------
__global__ void k_dw() {
    int gw = (blockIdx.x * blockDim.x + threadIdx.x) >> 5;
    int lane = threadIdx.x & 31;
    if (gw >= Nn * BL) return;
    int n = gw >> 16;
    int m = g_idx[gw];
    const float* xr = g_xt + (size_t)gw * 64;
    float* dwp = g_dw + ((size_t)n * Mm + m) * 64;
    atomicAdd(dwp + lane,      xr[lane]);
    atomicAdd(dwp + lane + 32, xr[lane + 32]);
}

// ---------------------------------------------------------------------------
__global__ void k_ema(const float* __restrict__ ema_count, float* __restrict__ out) {
    __shared__ float red[1024];
    int t = threadIdx.x;
    float perp = 0.0f;
    for (int n = 0; n < 4; n++) {
        float c = (float)g_cnt[n * Mm + t];
        float raw = DECAYF * ema_count[n * Mm + t] + (1.0f - DECAYF) * c;
        red[t] = raw; __syncthreads();
        for (int s = 512; s > 0; s >>= 1) { if (t < s) red[t] += red[t + s]; __syncthreads(); }
        float nsum = red[0]; __syncthreads();
        float fin = (raw + EPSF) / (nsum + Mm * EPSF) * nsum;
        out[OFF_CNT + n * Mm + t] = fin;
        g_fcnt[n * Mm + t] = fin;
        float avg = c * (1.0f / 65536.0f);
        float term = avg * logf(avg + 1e-10f);
        red[t] = term; __syncthreads();
        for (int s = 512; s > 0; s >>= 1) { if (t < s) red[t] += red[t + s]; __syncthreads(); }
        if (t == 0) perp += expf(-red[0]);
        __syncthreads();
    }
    if (t == 0) out[OFF_PERP] = perp;
}

// ---------------------------------------------------------------------------
__global__ void k_weight(const float* __restrict__ ema_weight, float* __restrict__ out) {
    int i = blockIdx.x * 256 + threadIdx.x;
    float w = DECAYF * ema_weight[i] + (1.0f - DECAYF) * g_dw[i];
    out[OFF_EMW + i] = w;
    out[OFF_EMB + i] = w / g_fcnt[i >> 6];
}

// ---------------------------------------------------------------------------
__global__ void k_gather(const float* __restrict__ x, const float* __restrict__ emb,
                         float* __restrict__ out) {
    __shared__ float se[16][68];
    __shared__ float red[256];
    int bn = blockIdx.x;
    int b = bn >> 2, n = bn & 3;
    int t = threadIdx.x;
    int r = t >> 4, c = t & 15;
    int idx = g_idx[n * BL + b * 16 + r];
    const float4* ep = (const float4*)emb + ((size_t)n * Mm + idx) * 16;
    float4 v = ep[c];
    se[r][c * 4] = v.x; se[r][c * 4 + 1] = v.y; se[r][c * 4 + 2] = v.z; se[r][c * 4 + 3] = v.w;
    __syncthreads();
    long long base = (long long)b * 4096 + n * 1024;
    float4 xv = ((const float4*)(x + base))[t];
    int lin = t * 4;
    int d = lin >> 4, l0 = lin & 15;
    float q0 = se[l0 + 0][d], q1 = se[l0 + 1][d], q2 = se[l0 + 2][d], q3 = se[l0 + 3][d];
    ((float4*)(out + OFF_ZQ + base))[t] = make_float4(q0, q1, q2, q3);
    float2* ez = (float2*)(out + OFF_EZQ + base);
    ez[2 * t]     = make_float2(q0, q1);
    ez[2 * t + 1] = make_float2(q2, q3);
    float d0 = xv.x - q0, d1 = xv.y - q1, d2 = xv.z - q2, d3 = xv.w - q3;
    red[t] = d0 * d0 + d1 * d1 + d2 * d2 + d3 * d3;
    __syncthreads();
    for (int s = 128; s > 0; s >>= 1) { if (t < s) red[t] += red[t + s]; __syncthreads(); }
    if (t == 0) g_losspart[bn] = red[0];
}

// ---------------------------------------------------------------------------
__global__ void k_loss(float* __restrict__ out) {
    __shared__ float red[1024];
    int t = threadIdx.x;
    float s = 0.0f;
    for (int i = t; i < Bb * Nn; i += 1024) s += g_losspart[i];
    red[t] = s; __syncthreads();
    for (int st = 512; st > 0; st >>= 1) { if (t < st) red[t] += red[t + st]; __syncthreads(); }
    if (t == 0) out[OFF_LOSS] = COMMITF * red[0] / 16777216.0f;
}

// ---------------------------------------------------------------------------
extern "C" void kernel_launch(void* const* d_in, const int* in_sizes, int n_in,
                              void* d_out, int out_size) {
    const float* x          = (const float*)d_in[0];
    const float* emb        = (const float*)d_in[1];
    const float* ema_count  = (const float*)d_in[2];
    const float* ema_weight = (const float*)d_in[3];
    float* out = (float*)d_out;

    cudaFuncSetAttribute(k_argmin, cudaFuncAttributeMaxDynamicSharedMemorySize, SM_BYTES);

    k_zero<<<1024, 256>>>();
    k_transpose<<<Bb * Nn, 256>>>(x);
    k_enorm<<<16, 256>>>(emb);
    dim3 ge(16, 4);
    k_et<<<ge, 256>>>(emb);
    dim3 ga(BL / 128, Nn);
    k_argmin<<<ga, 256, SM_BYTES>>>(out);
    k_dw<<<(Nn * BL) / 8, 256>>>();
    k_ema<<<1, 1024>>>(ema_count, out);
    k_weight<<<1024, 256>>>(ema_weight, out);
    k_gather<<<Bb * Nn, 256>>>(x, emb, out);
    k_loss<<<1, 1024>>>(out);
}